// round 15
// baseline (speedup 1.0000x reference)
#include <cuda_runtime.h>
#include <cuda_fp16.h>
#include <math.h>
#include <stdint.h>

#define MU    0.02f
#define MU2   (MU * MU)
#define NBINS 10
#define NMAX  4194304
#define NBMAX 2048
#define TPB   256
#define GQ    16384.0f        // g fixed-point scale (g < 4 -> gq < 65536)

// __device__ globals (allocation-free rule)
__device__ float        d_blk_min[NBMAX];
__device__ float        d_blk_max[NBMAX];
__device__ double       d_blk_loss[NBMAX][NBINS];
__device__ unsigned int d_blk_cnt[NBMAX][NBINS];
__device__ unsigned int d_bar;                        // monotonic ticket (never reset)
__device__ unsigned int d_done;                       // reset by last block each launch

// ---------------------------------------------------------------------------
// Software grid barrier: monotonic ticket counter, wrap-safe compare.
// Safe across graph replays (no reset). Requires all blocks resident
// (guaranteed: launch_bounds(256,8), grid = 8*SMs, 14.2KB smem/block).
__device__ __forceinline__ void grid_barrier() {
    __syncthreads();
    if (threadIdx.x == 0) {
        __threadfence();
        unsigned int ticket = atomicAdd(&d_bar, 1u);
        unsigned int target = (ticket / gridDim.x + 1u) * gridDim.x;
        while ((int)(*(volatile unsigned int*)&d_bar - target) < 0) { }
        __threadfence();
    }
    __syncthreads();
}

// Math per row: rsqrt-based (MUFU.RSQ), ~2e-7 rel err.
__device__ __forceinline__ void row_gl(float4 a, float4 b, float& g, float& loss) {
    float d0 = a.x - b.x, d1 = a.y - b.y, d2 = a.z - b.z, d3 = a.w - b.w;
    float x0 = fmaf(d0, d0, MU2), x1 = fmaf(d1, d1, MU2);
    float x2 = fmaf(d2, d2, MU2), x3 = fmaf(d3, d3, MU2);
    float r0 = rsqrtf(x0), r1 = rsqrtf(x1), r2 = rsqrtf(x2), r3 = rsqrtf(x3);
    loss = ((x0 * r0 - MU) + (x1 * r1 - MU)) + ((x2 * r2 - MU) + (x3 * r3 - MU));
    g    = ((fabsf(d0) * r0 + fabsf(d1) * r1) + (fabsf(d2) * r2 + fabsf(d3) * r3));
}

// Pack one row: u16 trunc(g*16384) | fp16(loss) << 16. (Validated R14: 1e-5.)
__device__ __forceinline__ unsigned int pack_row(float g, float l) {
    unsigned int gq = (unsigned int)fminf(g * GQ, 65535.0f);
    unsigned int hb = (unsigned int)__half_as_ushort(__float2half_rn(l));
    return gq | (hb << 16);
}

// ---------------------------------------------------------------------------
__global__ __launch_bounds__(TPB, 8)
void ghmr_fused(const float4* __restrict__ in, const float4* __restrict__ tg,
                float* __restrict__ out, int n, int rpb) {
    extern __shared__ unsigned int s_pk[];             // rpb packed rows
    const int lane = threadIdx.x & 31;
    const int wid  = threadIdx.x >> 5;

    __shared__ float s_w0[8], s_w1[8];
    __shared__ float s_scale;
    __shared__ int   s_last;

    const int base = blockIdx.x * rpb;
    const int end  = min(base + rpb, n);               // may be <= base (guarded loops)

    // ============ Phase A: stream input, pack into OWN smem, min/max ==========
    float lmin = __int_as_float(0x7F800000);           // +inf
    float lmax = 0.0f;

    for (int i = base + threadIdx.x; i < end; i += TPB) {
        float4 a = __ldcs(&in[i]);
        float4 b = __ldcs(&tg[i]);
        float g, l;
        row_gl(a, b, g, l);
        s_pk[i - base] = pack_row(g, l);               // STS, conflict-free
        lmin = fminf(lmin, g);
        lmax = fmaxf(lmax, g);
    }

    #pragma unroll
    for (int o = 16; o > 0; o >>= 1) {
        lmin = fminf(lmin, __shfl_xor_sync(0xFFFFFFFFu, lmin, o));
        lmax = fmaxf(lmax, __shfl_xor_sync(0xFFFFFFFFu, lmax, o));
    }
    if (lane == 0) { s_w0[wid] = lmin; s_w1[wid] = lmax; }
    __syncthreads();
    if (threadIdx.x == 0) {
        float gm = s_w0[0], gM = s_w1[0];
        #pragma unroll
        for (int w = 1; w < 8; w++) { gm = fminf(gm, s_w0[w]); gM = fmaxf(gM, s_w1[w]); }
        d_blk_min[blockIdx.x] = gm;                    // plain overwrite, no init
        d_blk_max[blockIdx.x] = gM;
    }

    grid_barrier();                                    // publishes slots (fences inside)

    // ============ Every block reduces the slots for the global range ==========
    {
        float m = __int_as_float(0x7F800000), M = 0.0f;
        for (int r = threadIdx.x; r < (int)gridDim.x; r += TPB) {
            m = fminf(m, d_blk_min[r]);
            M = fmaxf(M, d_blk_max[r]);
        }
        #pragma unroll
        for (int o = 16; o > 0; o >>= 1) {
            m = fminf(m, __shfl_xor_sync(0xFFFFFFFFu, m, o));
            M = fmaxf(M, __shfl_xor_sync(0xFFFFFFFFu, M, o));
        }
        __syncthreads();                               // s_w0/s_w1 reuse
        if (lane == 0) { s_w0[wid] = m; s_w1[wid] = M; }
        __syncthreads();
        if (threadIdx.x == 0) {
            float gm = s_w0[0], gM = s_w1[0];
            #pragma unroll
            for (int w = 1; w < 8; w++) { gm = fminf(gm, s_w0[w]); gM = fmaxf(gM, s_w1[w]); }
            s_scale = (10.0f / (gM - gm)) * (1.0f / GQ);   // bins from quantized g
        }
        __syncthreads();
    }
    const float scale2 = s_scale;

    // ============ Phase B: histogram own smem slice (LDS-fed) ================
    float acc[NBINS];
    #pragma unroll
    for (int k = 0; k < NBINS; k++) acc[k] = 0.0f;
    unsigned long long c64 = 0ull;                     // 6 bits/bin; <=14 rows/thread

    const int cnt = end - base;
    for (int i = threadIdx.x; i < cnt; i += TPB) {
        unsigned int w = s_pk[i];
        float gq = (float)(w & 0xFFFFu);
        float lf = __half2float(__ushort_as_half((unsigned short)(w >> 16)));
        int b = min((int)(gq * scale2), NBINS - 1);    // gq >= 0: no lower clamp
        #pragma unroll
        for (int k = 0; k < NBINS; k++) {
            if (k == b) acc[k] += lf;
        }
        c64 += (1ull << (6 * b));
    }

    // two-level reduction, write per-block slots
    __shared__ float        s_acc[8][NBINS];
    __shared__ unsigned int s_cnt[8][NBINS];
    #pragma unroll
    for (int b = 0; b < NBINS; b++) {
        float        a = acc[b];
        unsigned int c = (unsigned int)((c64 >> (6 * b)) & 63ull);
        #pragma unroll
        for (int o = 16; o > 0; o >>= 1) {
            a += __shfl_xor_sync(0xFFFFFFFFu, a, o);
            c += __shfl_xor_sync(0xFFFFFFFFu, c, o);
        }
        if (lane == 0) { s_acc[wid][b] = a; s_cnt[wid][b] = c; }
    }
    __syncthreads();
    if (threadIdx.x < NBINS) {
        double       s = 0.0;
        unsigned int c = 0u;
        #pragma unroll
        for (int w = 0; w < 8; w++) { s += (double)s_acc[w][threadIdx.x]; c += s_cnt[w][threadIdx.x]; }
        d_blk_loss[blockIdx.x][threadIdx.x] = s;
        d_blk_cnt[blockIdx.x][threadIdx.x]  = c;
        __threadfence();                               // publish slots
    }
    __syncthreads();
    if (threadIdx.x == 0)
        s_last = (atomicAdd(&d_done, 1u) == (unsigned)(gridDim.x - 1));
    __syncthreads();

    // ============ Last finishing block finalizes =============================
    if (s_last) {
        __threadfence();                               // acquire all slots
        __shared__ double s_con[NBINS];
        __shared__ int    s_ne[NBINS];

        for (int b = wid; b < NBINS; b += 8) {         // warps cover the 10 bins
            double       s = 0.0;
            unsigned int c = 0u;
            for (int r = lane; r < (int)gridDim.x; r += 32) {
                s += d_blk_loss[r][b];
                c += d_blk_cnt[r][b];
            }
            #pragma unroll
            for (int o = 16; o > 0; o >>= 1) {
                s += __shfl_xor_sync(0xFFFFFFFFu, s, o);
                c += __shfl_xor_sync(0xFFFFFFFFu, c, o);
            }
            if (lane == 0) {
                s_con[b] = (c > 0u) ? s / (double)c : 0.0;   // parallel DDIVs
                s_ne[b]  = (c > 0u) ? 1 : 0;
            }
        }
        __syncthreads();
        if (threadIdx.x == 0) {
            double s = 0.0;
            int    ne = 0;
            #pragma unroll
            for (int b = 0; b < NBINS; b++) { s += s_con[b]; ne += s_ne[b]; }
            if (ne < 1) ne = 1;
            out[0] = (float)(s / (double)ne / 64.0 / 4096.0);
            d_done = 0u;                               // reset for next replay
            __threadfence();
        }
    }
}

// ---------------------------------------------------------------------------
extern "C" void kernel_launch(void* const* d_in, const int* in_sizes, int n_in,
                              void* d_out, int out_size) {
    const float4* in = (const float4*)d_in[0];
    const float4* tg = (const float4*)d_in[1];
    int n = in_sizes[0] / 4;           // rows (channels = 4)
    if (n > NMAX) n = NMAX;

    int sm = 0;
    if (cudaDeviceGetAttribute(&sm, cudaDevAttrMultiProcessorCount, 0) != cudaSuccess || sm <= 0)
        sm = 148;
    int nb = 8 * sm;                   // launch_bounds(256,8) => all co-resident
    if (nb > NBMAX) nb = NBMAX;

    int rpb = (n + nb - 1) / nb;       // rows per block (~3543 @ n=4.19M, sm=148)
    size_t smem = ((size_t)rpb * 4u + 127u) & ~127u;   // ~14.2 KB < 48 KB default

    ghmr_fused<<<nb, TPB, smem>>>(in, tg, (float*)d_out, n, rpb);
}